// round 14
// baseline (speedup 1.0000x reference)
#include <cuda_runtime.h>
#include <cuda_fp16.h>
#include <cstdint>

#define DEV __device__ __forceinline__

namespace {
constexpr int NPTS = 131072;
constexpr int MT = 128;
constexpr int THREADS = 544;  // 16 compute warps (4 groups of 4) + 1 producer
constexpr int CTH = 512;
constexpr int KC = 64;
constexpr int AS = 264;       // activation row stride (halves)
constexpr int WS = 72;        // weight/feat row stride (halves)
constexpr float TWO_PI = 6.2831853071795864769f;

constexpr int CH_H = 256 * WS;       // 18432 halves per chunk
constexpr uint32_t CH_B = CH_H * 2;  // 36864 B
constexpr int L0_CHUNKS = 8;         // K0=512 (sin/cos; coords in epilogue)
constexpr int N_CHUNKS = L0_CHUNKS + 32;

constexpr int H_STRIDE = MT * AS;
constexpr uint32_t H_BYTES = H_STRIDE * 2;

// SMEM map (bytes)
constexpr int OFF_ACT   = 0;                 // 67584 (in-place; feat overlaid)
constexpr int FEAT_SZ   = 128 * WS * 2;      // 18432
constexpr int OFF_WRING = 67584;             // 4 * 36864
constexpr int OFF_SX    = 215040;            // 2048
constexpr int OFF_SB    = 217088;            // 3072
constexpr int OFF_TAIL  = 220160;            // 3072 (W0 rows 0..2)
constexpr int OFF_OUTAC = 223232;            // 2048
constexpr int OFF_FULL  = 225280;            // 4 x 8
constexpr int OFF_EMPTY = 225312;            // 4 x 8
constexpr int OFF_HBAR  = 225344;            // 8
constexpr int SMEM_BYTES = 225408;
}

__device__ __half g_Wt[(size_t)N_CHUNKS * CH_H];
__device__ __half g_h[(size_t)(NPTS / MT) * H_STRIDE];

// ---------------- helpers ----------------
DEV uint32_t smem_u32(const void* p) {
  uint32_t a;
  asm("{ .reg .u64 t; cvta.to.shared.u64 t, %1; cvt.u32.u64 %0, t; }" : "=r"(a) : "l"(p));
  return a;
}
#define MBAR_INIT(mb, c) \
  asm volatile("mbarrier.init.shared.b64 [%0], %1;" :: "r"(mb), "r"(c) : "memory")
#define MBAR_ARRIVE(mb) \
  asm volatile("mbarrier.arrive.shared.b64 _, [%0];" :: "r"(mb) : "memory")
#define MBAR_WAIT(mb, ph) do {                                                        \
  uint32_t _m = (mb), _p = (uint32_t)(ph), _d;                                        \
  asm volatile("{ .reg .pred p; mbarrier.try_wait.parity.acquire.cta.shared::cta.b64 p, [%1], %2; selp.b32 %0,1,0,p; }" \
               : "=r"(_d) : "r"(_m), "r"(_p) : "memory");                             \
  if (!_d) {                                                                          \
    asm volatile("{ .reg .pred P1; WL%=: mbarrier.try_wait.parity.acquire.cta.shared::cta.b64 P1, [%0], %1, 0x989680; @P1 bra.uni WD%=; bra.uni WL%=; WD%=: }" \
                 :: "r"(_m), "r"(_p) : "memory");                                     \
  }                                                                                   \
} while (0)

DEV void barsync_all() { asm volatile("bar.sync 1, 512;" ::: "memory"); }
DEV void grpbar(int wm) { asm volatile("bar.sync %0, 128;" :: "r"(2 + wm) : "memory"); }

DEV void issue_bulk(uint32_t dst32, const void* src, uint32_t nbytes, uint32_t mbar) {
  asm volatile("mbarrier.arrive.expect_tx.shared.b64 _, [%0], %1;"
               :: "r"(mbar), "r"(nbytes) : "memory");
  asm volatile(
      "cp.async.bulk.shared::cta.global.mbarrier::complete_tx::bytes [%0], [%1], %2, [%3];"
      :: "r"(dst32), "l"(src), "r"(nbytes), "r"(mbar) : "memory");
}

DEV void ldsm4(uint32_t* r, uint32_t addr) {
  asm volatile("ldmatrix.sync.aligned.m8n8.x4.shared.b16 {%0,%1,%2,%3}, [%4];"
               : "=r"(r[0]), "=r"(r[1]), "=r"(r[2]), "=r"(r[3]) : "r"(addr));
}
DEV void mma16816(float* d, const uint32_t* a, uint32_t b0, uint32_t b1) {
  asm volatile(
      "mma.sync.aligned.m16n8k16.row.col.f32.f16.f16.f32 "
      "{%0,%1,%2,%3}, {%4,%5,%6,%7}, {%8,%9}, {%0,%1,%2,%3};\n"
      : "+f"(d[0]), "+f"(d[1]), "+f"(d[2]), "+f"(d[3])
      : "r"(a[0]), "r"(a[1]), "r"(a[2]), "r"(a[3]), "r"(b0), "r"(b1));
}
DEV float frelu(float v) { return fmaxf(v, 0.0f); }
DEV uint32_t pack2(float a, float b) {
  __half2 h = __floats2half2_rn(a, b);
  return *reinterpret_cast<uint32_t*>(&h);
}

// ---------------- prep ----------------
__global__ void prep_weights(const float* W0, const float* W1, const float* W2,
                             const float* W3, const float* W4, const float* Wc0,
                             const float* Wc1, const float* Wn0, const float* Wn1) {
  int e = blockIdx.x * blockDim.x + threadIdx.x;
  constexpr int TOTAL = N_CHUNKS * CH_H;
  if (e >= TOTAL) return;
  int chunk = e / CH_H, r = e % CH_H, n = r / WS, kk = r % WS;
  float v = 0.0f;
  if (kk < KC) {
    if (chunk < L0_CHUNKS) {
      int k = chunk * KC + kk;
      v = W0[(k + 3) * 256 + n];
    } else {
      int c2 = chunk - L0_CHUNKS;
      int l = c2 >> 2, k = (c2 & 3) * KC + kk;
      const float* Ws[8] = {W1, W2, W3, W4, Wc0, Wc1, Wn0, Wn1};
      v = Ws[l][k * 256 + n];
    }
  }
  g_Wt[e] = __float2half(v);
}

// ---------------- fused kernel ----------------
struct Params {
  const float *x, *B, *W0;
  const float *b0, *b1, *b2, *b3, *b4, *bc0, *bc1, *bc2, *bn0, *bn1, *bn2;
  const float *Wc2, *Wn2;
  const int* t;
  float* out;
};

struct Ctx {
  char* smem;
  uint32_t act32, wring32, full32, empty32;
  int tid, wm, wn, lrow, lk, grp, qp, lane;
};

DEV void gen_feat(const Ctx& cx, int c, float tot) {
  const float* sx = (const float*)(cx.smem + OFF_SX);
  const float* sB = (const float*)(cx.smem + OFF_SB);
  __half* dst = (__half*)(cx.smem + OFF_ACT + (c & 1) * FEAT_SZ);
  const int kk = cx.tid & 63;
  const int mb = cx.tid >> 6;
  const int kg = c * KC + kk;
  const bool issin = kg < 256;
  const int j = kg & 255;
  const float Bx = sB[j], By = sB[256 + j], Bz = sB[512 + j];
  const float a = fminf(fmaxf(tot - (float)j, 0.0f), 1.0f);
#pragma unroll
  for (int i = 0; i < 16; i++) {
    const int m = mb + i * 8;
    float px = sx[m * 4] * Bx;
    px = fmaf(sx[m * 4 + 1], By, px);
    px = fmaf(sx[m * 4 + 2], Bz, px);
    float arg = px * TWO_PI;
    float qf = rintf(arg * 0.3183098861837907f);
    float r = fmaf(qf, -3.1414794921875f, arg);
    r = fmaf(qf, -1.1315941810607910156e-4f, r);
    r = fmaf(qf, -1.9841872589410058936e-9f, r);
    float v = issin ? __sinf(r) : __cosf(r);
    if (((int)qf) & 1) v = -v;
    dst[m * WS + kk] = __float2half(v * a);
  }
}

// Software-pipelined KC=64 chunk (parity-double-buffered fragments).
DEV void chunk_mma(const Ctx& cx, uint32_t aBase, int ast, int kb, uint32_t wslot,
                   float acc[2][8][4]) {
  const uint32_t aA0 = aBase + ((cx.wm * 32 + cx.lrow) * ast + kb + cx.lk) * 2;
  const uint32_t bA0 = wslot + ((cx.wn * 64 + cx.lrow) * WS + cx.lk) * 2;
  uint32_t a0[2][4], a1[2][4], bb[2][4];
  ldsm4(a0[0], aA0);
  ldsm4(a1[0], aA0 + 16 * ast * 2);
  ldsm4(bb[0], bA0);
#pragma unroll
  for (int s = 0; s < 16; s++) {
    const int ks = s >> 2, np = s & 3;
    const int cur = s & 1, kpar = ks & 1;
    if (s + 1 < 16) {
      const int ks2 = (s + 1) >> 2, np2 = (s + 1) & 3;
      ldsm4(bb[cur ^ 1], bA0 + ks2 * 32 + np2 * (16 * WS * 2));
    }
    if (np == 2 && ks + 1 < 4) {
      ldsm4(a0[kpar ^ 1], aA0 + (ks + 1) * 32);
      ldsm4(a1[kpar ^ 1], aA0 + (ks + 1) * 32 + 16 * ast * 2);
    }
    mma16816(acc[0][2 * np],     a0[kpar], bb[cur][0], bb[cur][2]);
    mma16816(acc[0][2 * np + 1], a0[kpar], bb[cur][1], bb[cur][3]);
    mma16816(acc[1][2 * np],     a1[kpar], bb[cur][0], bb[cur][2]);
    mma16816(acc[1][2 * np + 1], a1[kpar], bb[cur][1], bb[cur][3]);
  }
}

// MODE 0: act in-place. MODE 1: color head (dot Wc2, write out). MODE 2: displ head.
// Sync scope: per-wm-group named barrier (128 threads) — bands are disjoint.
template <int MODE, bool SAVEH>
__device__ __noinline__ void layerSq(const Ctx& cx, int base, const float* gbias,
                                     __half* gh, const Params& p, int m0) {
  float* outac = (float*)(cx.smem + OFF_OUTAC);
  __half* act = (__half*)(cx.smem + OFF_ACT);

  float acc[2][8][4];
#pragma unroll
  for (int a = 0; a < 2; a++)
#pragma unroll
    for (int b = 0; b < 8; b++)
#pragma unroll
      for (int d = 0; d < 4; d++) acc[a][b][d] = 0.0f;

#pragma unroll
  for (int cp = 0; cp < 2; cp++) {
    const int g0 = base + 2 * cp, g1 = g0 + 1;
    const int s0 = g0 & 3, s1 = g1 & 3;
    MBAR_WAIT(cx.full32 + s0 * 8, (g0 >> 2) & 1);
    MBAR_WAIT(cx.full32 + s1 * 8, (g1 >> 2) & 1);
    chunk_mma(cx, cx.act32, AS, (2 * cp) * KC, cx.wring32 + s0 * CH_B, acc);
    if (cx.lane == 0) MBAR_ARRIVE(cx.empty32 + s0 * 8);
    chunk_mma(cx, cx.act32, AS, (2 * cp + 1) * KC, cx.wring32 + s1 * CH_B, acc);
    if (cx.lane == 0) MBAR_ARRIVE(cx.empty32 + s1 * 8);
  }
  grpbar(cx.wm);  // band-local in-place hazard

  if (MODE == 0) {
    const float2* gb2 = (const float2*)gbias;
#pragma unroll
    for (int mt = 0; mt < 2; mt++) {
      const int r0 = cx.wm * 32 + mt * 16 + cx.grp;
#pragma unroll
      for (int nt = 0; nt < 8; nt++) {
        const int col = cx.wn * 64 + nt * 8 + cx.qp * 2;
        float2 b2 = gb2[col >> 1];
        uint32_t lo = pack2(frelu(acc[mt][nt][0] + b2.x), frelu(acc[mt][nt][1] + b2.y));
        uint32_t hi = pack2(frelu(acc[mt][nt][2] + b2.x), frelu(acc[mt][nt][3] + b2.y));
        *(uint32_t*)(act + r0 * AS + col) = lo;
        *(uint32_t*)(act + (r0 + 8) * AS + col) = hi;
        if (SAVEH) {
          *(uint32_t*)(gh + r0 * AS + col) = lo;
          *(uint32_t*)(gh + (r0 + 8) * AS + col) = hi;
        }
      }
    }
    grpbar(cx.wm);
  } else {
    const float2* gb2 = (const float2*)gbias;
    constexpr int NJ = (MODE == 1) ? 3 : 1;
    float part[2][2][NJ];
#pragma unroll
    for (int a = 0; a < 2; a++)
#pragma unroll
      for (int b = 0; b < 2; b++)
#pragma unroll
        for (int j = 0; j < NJ; j++) part[a][b][j] = 0.0f;
#pragma unroll
    for (int nt = 0; nt < 8; nt++) {
      const int col = cx.wn * 64 + nt * 8 + cx.qp * 2;
      float2 b2 = gb2[col >> 1];
      float w0[NJ], w1[NJ];
#pragma unroll
      for (int j = 0; j < NJ; j++) {
        w0[j] = (MODE == 1) ? p.Wc2[col * 3 + j] : p.Wn2[col];
        w1[j] = (MODE == 1) ? p.Wc2[(col + 1) * 3 + j] : p.Wn2[col + 1];
      }
#pragma unroll
      for (int mt = 0; mt < 2; mt++) {
        float v0 = frelu(acc[mt][nt][0] + b2.x), v1 = frelu(acc[mt][nt][1] + b2.y);
        float v2 = frelu(acc[mt][nt][2] + b2.x), v3 = frelu(acc[mt][nt][3] + b2.y);
#pragma unroll
        for (int j = 0; j < NJ; j++) {
          part[mt][0][j] += v0 * w0[j] + v1 * w1[j];
          part[mt][1][j] += v2 * w0[j] + v3 * w1[j];
        }
      }
    }
#pragma unroll
    for (int mt = 0; mt < 2; mt++)
#pragma unroll
      for (int rh = 0; rh < 2; rh++)
#pragma unroll
        for (int j = 0; j < NJ; j++) {
          float v = part[mt][rh][j];
          v += __shfl_xor_sync(0xffffffffu, v, 1);
          v += __shfl_xor_sync(0xffffffffu, v, 2);
          if (cx.qp == 0)
            atomicAdd(&outac[(cx.wm * 32 + mt * 16 + rh * 8 + cx.grp) * 4 + j], v);
        }
    grpbar(cx.wm);  // atomics visible within group
    const int lt = cx.tid & 127;  // group-local tid
    if (MODE == 1) {
      if (lt < 96) {
        int ml = lt / 3, j = lt - ml * 3;
        int row = cx.wm * 32 + ml;
        float v = outac[row * 4 + j];
        outac[row * 4 + j] = 0.0f;  // re-zero for displacement head
        p.out[(m0 + row) * 3 + j] = tanhf(v + p.bc2[j]) * 0.5f;
      }
    } else {
      if (lt < 32) {
        int row = cx.wm * 32 + lt;
        p.out[3 * NPTS + m0 + row] = tanhf(outac[row * 4] + p.bn2[0]) * 0.1f;
      }
    }
    grpbar(cx.wm);
  }
}

__global__ void __launch_bounds__(THREADS, 1) fused_mlp(Params p) {
  extern __shared__ char smem[];
  Ctx cx;
  cx.smem = smem;
  cx.tid = threadIdx.x;
  cx.lane = cx.tid & 31;
  const int wid = cx.tid >> 5;
  cx.wm = (wid >> 2) & 3; cx.wn = wid & 3;
  cx.lrow = cx.lane & 15; cx.lk = (cx.lane >> 4) << 3;
  cx.grp = cx.lane >> 2; cx.qp = cx.lane & 3;
  cx.act32 = smem_u32(smem + OFF_ACT);
  cx.wring32 = smem_u32(smem + OFF_WRING);
  cx.full32 = smem_u32(smem + OFF_FULL);
  cx.empty32 = smem_u32(smem + OFF_EMPTY);
  const uint32_t hbar32 = smem_u32(smem + OFF_HBAR);

  const int m0 = blockIdx.x * MT;
  __half* gh = g_h + (size_t)blockIdx.x * H_STRIDE;
  float* sx = (float*)(smem + OFF_SX);
  float* sB = (float*)(smem + OFF_SB);
  float* stail = (float*)(smem + OFF_TAIL);
  float* outac = (float*)(smem + OFF_OUTAC);
  __half* act = (__half*)(smem + OFF_ACT);

  if (cx.tid == 0) {
#pragma unroll
    for (int s = 0; s < 4; s++) {
      MBAR_INIT(cx.full32 + s * 8, 1);
      MBAR_INIT(cx.empty32 + s * 8, 16);
    }
    MBAR_INIT(hbar32, 1);
  }
  if (cx.tid < 384) {
    int m = cx.tid / 3, d = cx.tid - m * 3;
    sx[m * 4 + d] = p.x[(m0 + m) * 3 + d];
  }
  for (int i = cx.tid; i < 768; i += THREADS) {
    sB[i] = p.B[i];
    stail[i] = p.W0[i];
  }
  if (cx.tid < CTH) outac[cx.tid] = 0.0f;
  __syncthreads();

  if (wid == 16) {  // ---- producer warp ----
    if (cx.lane == 0) {
      for (int i = 0; i < N_CHUNKS; i++) {
        int s = i & 3;
        MBAR_WAIT(cx.empty32 + s * 8, 1 ^ ((i >> 2) & 1));
        issue_bulk(cx.wring32 + s * CH_B, g_Wt + (size_t)i * CH_H, CH_B, cx.full32 + s * 8);
      }
    }
    return;
  }

  // ---- consumers ----
  int tbits = *p.t;
  float tval = (tbits >= 0 && tbits < (1 << 20)) ? (float)tbits : __int_as_float(tbits);
  const float tot = tval * (6000.0f / 512.0f);  // t / TAU

  // Layer 0 (full-CTA barriers: feat generation is cross-band)
  {
    float acc[2][8][4];
#pragma unroll
    for (int a = 0; a < 2; a++)
#pragma unroll
      for (int b = 0; b < 8; b++)
#pragma unroll
        for (int d = 0; d < 4; d++) acc[a][b][d] = 0.0f;
    gen_feat(cx, 0, tot);
    for (int c = 0; c < L0_CHUNKS; c++) {
      barsync_all();
      const int s = c & 3;
      MBAR_WAIT(cx.full32 + s * 8, (c >> 2) & 1);
      chunk_mma(cx, cx.act32 + (c & 1) * FEAT_SZ, WS, 0, cx.wring32 + s * CH_B, acc);
      if (cx.lane == 0) MBAR_ARRIVE(cx.empty32 + s * 8);
      if (c + 1 < L0_CHUNKS) gen_feat(cx, c + 1, tot);
    }
    barsync_all();
    const float2* gb2 = (const float2*)p.b0;
#pragma unroll
    for (int mt = 0; mt < 2; mt++) {
      const int r0 = cx.wm * 32 + mt * 16 + cx.grp;
      const float x0a = sx[r0 * 4], x1a = sx[r0 * 4 + 1], x2a = sx[r0 * 4 + 2];
      const float x0b = sx[(r0 + 8) * 4], x1b = sx[(r0 + 8) * 4 + 1], x2b = sx[(r0 + 8) * 4 + 2];
#pragma unroll
      for (int nt = 0; nt < 8; nt++) {
        const int col = cx.wn * 64 + nt * 8 + cx.qp * 2;
        float w00 = stail[col], w01 = stail[col + 1];
        float w10 = stail[256 + col], w11 = stail[256 + col + 1];
        float w20 = stail[512 + col], w21 = stail[512 + col + 1];
        float c0 = fmaf(x0a, w00, fmaf(x1a, w10, x2a * w20));
        float c1 = fmaf(x0a, w01, fmaf(x1a, w11, x2a * w21));
        float c2 = fmaf(x0b, w00, fmaf(x1b, w10, x2b * w20));
        float c3 = fmaf(x0b, w01, fmaf(x1b, w11, x2b * w21));
        float2 b2 = gb2[col >> 1];
        *(uint32_t*)(act + r0 * AS + col) =
            pack2(frelu(acc[mt][nt][0] + c0 + b2.x), frelu(acc[mt][nt][1] + c1 + b2.y));
        *(uint32_t*)(act + (r0 + 8) * AS + col) =
            pack2(frelu(acc[mt][nt][2] + c2 + b2.x), frelu(acc[mt][nt][3] + c3 + b2.y));
      }
    }
    barsync_all();
  }

  layerSq<0, false>(cx,  8, p.b1,  nullptr, p, m0);  // l1
  layerSq<0, false>(cx, 12, p.b2,  nullptr, p, m0);  // l2
  layerSq<0, false>(cx, 16, p.b3,  nullptr, p, m0);  // l3
  layerSq<0, true >(cx, 20, p.b4,  gh,      p, m0);  // l4 -> h to act + g_h
  layerSq<0, false>(cx, 24, p.bc0, nullptr, p, m0);  // l5
  layerSq<1, false>(cx, 28, p.bc1, nullptr, p, m0);  // l6 color head

  // restore h (cross-band TMA write into act): full sync around it
  barsync_all();
  if (cx.tid == 0) {
    asm volatile("fence.proxy.async;" ::: "memory");
    issue_bulk(cx.act32, gh, H_BYTES, hbar32);
  }
  MBAR_WAIT(hbar32, 0);

  layerSq<0, false>(cx, 32, p.bn0, nullptr, p, m0);  // l7
  layerSq<2, false>(cx, 36, p.bn1, nullptr, p, m0);  // l8 displacement head
}

extern "C" void kernel_launch(void* const* d_in, const int* in_sizes, int n_in,
                              void* d_out, int out_size) {
  int i = 0;
  const float* x = (const float*)d_in[i++];
  const float* B = (const float*)d_in[i++];
  const void* tp = nullptr;
  if (in_sizes[2] == 1) tp = d_in[i++];  // dict order: t at index 2
  const float *W[11], *bias[11];
  for (int j = 0; j < 11; j++) {
    W[j] = (const float*)d_in[i++];
    bias[j] = (const float*)d_in[i++];
  }
  if (!tp && i < n_in) tp = d_in[i++];

  cudaFuncSetAttribute(fused_mlp, cudaFuncAttributeMaxDynamicSharedMemorySize, SMEM_BYTES);

  constexpr int TOTAL = N_CHUNKS * CH_H;
  prep_weights<<<(TOTAL + 255) / 256, 256>>>(W[0], W[1], W[2], W[3], W[4],
                                             W[5], W[6], W[8], W[9]);

  Params p;
  p.x = x; p.B = B; p.W0 = W[0];
  p.b0 = bias[0]; p.b1 = bias[1]; p.b2 = bias[2]; p.b3 = bias[3]; p.b4 = bias[4];
  p.bc0 = bias[5]; p.bc1 = bias[6]; p.bc2 = bias[7];
  p.bn0 = bias[8]; p.bn1 = bias[9]; p.bn2 = bias[10];
  p.Wc2 = W[7]; p.Wn2 = W[10];
  p.t = (const int*)tp;
  p.out = (float*)d_out;

  fused_mlp<<<NPTS / MT, THREADS, SMEM_BYTES>>>(p);
}

// round 15
// speedup vs baseline: 1.1718x; 1.1718x over previous
#include <cuda_runtime.h>
#include <cuda_fp16.h>
#include <cstdint>

#define DEV __device__ __forceinline__

namespace {
constexpr int NPTS = 131072;
constexpr int MT = 128;
constexpr int THREADS = 544;  // 16 compute warps (4Mx4N) + 1 producer warp
constexpr int CTH = 512;
constexpr int KC = 64;
constexpr int AS = 264;       // activation row stride (halves)
constexpr int WS = 72;        // weight/feat row stride (halves)
constexpr float TWO_PI = 6.2831853071795864769f;

constexpr int CH_H = 256 * WS;       // 18432 halves per chunk
constexpr uint32_t CH_B = CH_H * 2;  // 36864 B
constexpr int L0_CHUNKS = 8;         // K0=512 (sin/cos; coords in epilogue)
constexpr int N_CHUNKS = L0_CHUNKS + 32;  // 40

// SMEM map (bytes)
constexpr int OFF_ACTA  = 0;                 // 67584
constexpr int OFF_ACTB  = 67584;             // 67584 (L0 feat buffers live here)
constexpr int FEAT_SZ   = 128 * WS * 2;      // 18432
constexpr int OFF_WRING = 135168;            // 2 * 36864 = 73728
constexpr int OFF_UNION = 208896;            // L0: sx+sB | heads: Wc2+Wn2
constexpr int OFF_SX    = OFF_UNION;         // 2048
constexpr int OFF_SB    = OFF_UNION + 2048;  // 3072
constexpr int OFF_WC2   = OFF_UNION;         // 3072 (overlay after L0)
constexpr int OFF_WN2   = OFF_UNION + 3072;  // 1024
constexpr int OFF_TAIL  = 214016;            // 3072 (W0 rows 0..2)
constexpr int OFF_BIAS  = 217088;            // 2 x 1024
constexpr int OFF_OUTAC = 219136;            // 2048
constexpr int OFF_FULL  = 221184;            // 2 x 8
constexpr int OFF_EMPTY = 221200;            // 2 x 8
constexpr int SMEM_BYTES = 221248;
}

__device__ __half g_Wt[(size_t)N_CHUNKS * CH_H];

// ---------------- helpers ----------------
DEV uint32_t smem_u32(const void* p) {
  uint32_t a;
  asm("{ .reg .u64 t; cvta.to.shared.u64 t, %1; cvt.u32.u64 %0, t; }" : "=r"(a) : "l"(p));
  return a;
}
#define MBAR_INIT(mb, c) \
  asm volatile("mbarrier.init.shared.b64 [%0], %1;" :: "r"(mb), "r"(c) : "memory")
#define MBAR_ARRIVE(mb) \
  asm volatile("mbarrier.arrive.shared.b64 _, [%0];" :: "r"(mb) : "memory")
#define MBAR_WAIT(mb, ph) do {                                                        \
  uint32_t _m = (mb), _p = (uint32_t)(ph), _d;                                        \
  asm volatile("{ .reg .pred p; mbarrier.try_wait.parity.acquire.cta.shared::cta.b64 p, [%1], %2; selp.b32 %0,1,0,p; }" \
               : "=r"(_d) : "r"(_m), "r"(_p) : "memory");                             \
  if (!_d) {                                                                          \
    asm volatile("{ .reg .pred P1; WL%=: mbarrier.try_wait.parity.acquire.cta.shared::cta.b64 P1, [%0], %1, 0x989680; @P1 bra.uni WD%=; bra.uni WL%=; WD%=: }" \
                 :: "r"(_m), "r"(_p) : "memory");                                     \
  }                                                                                   \
} while (0)

DEV void barsync() { asm volatile("bar.sync 1, 512;" ::: "memory"); }

DEV void issue_bulk(uint32_t dst32, const void* src, uint32_t nbytes, uint32_t mbar) {
  asm volatile("mbarrier.arrive.expect_tx.shared.b64 _, [%0], %1;"
               :: "r"(mbar), "r"(nbytes) : "memory");
  asm volatile(
      "cp.async.bulk.shared::cta.global.mbarrier::complete_tx::bytes [%0], [%1], %2, [%3];"
      :: "r"(dst32), "l"(src), "r"(nbytes), "r"(mbar) : "memory");
}

DEV void ldsm4(uint32_t* r, uint32_t addr) {
  asm volatile("ldmatrix.sync.aligned.m8n8.x4.shared.b16 {%0,%1,%2,%3}, [%4];"
               : "=r"(r[0]), "=r"(r[1]), "=r"(r[2]), "=r"(r[3]) : "r"(addr));
}
DEV void mma16816(float* d, const uint32_t* a, uint32_t b0, uint32_t b1) {
  asm volatile(
      "mma.sync.aligned.m16n8k16.row.col.f32.f16.f16.f32 "
      "{%0,%1,%2,%3}, {%4,%5,%6,%7}, {%8,%9}, {%0,%1,%2,%3};\n"
      : "+f"(d[0]), "+f"(d[1]), "+f"(d[2]), "+f"(d[3])
      : "r"(a[0]), "r"(a[1]), "r"(a[2]), "r"(a[3]), "r"(b0), "r"(b1));
}
DEV float frelu(float v) { return fmaxf(v, 0.0f); }
DEV uint32_t pack2(float a, float b) {
  __half2 h = __floats2half2_rn(a, b);
  return *reinterpret_cast<uint32_t*>(&h);
}

// ---------------- prep ----------------
__global__ void prep_weights(const float* W0, const float* W1, const float* W2,
                             const float* W3, const float* W4, const float* Wc0,
                             const float* Wc1, const float* Wn0, const float* Wn1) {
  int e = blockIdx.x * blockDim.x + threadIdx.x;
  constexpr int TOTAL = N_CHUNKS * CH_H;
  if (e >= TOTAL) return;
  int chunk = e / CH_H, r = e % CH_H, n = r / WS, kk = r % WS;
  float v = 0.0f;
  if (kk < KC) {
    if (chunk < L0_CHUNKS) {
      int k = chunk * KC + kk;
      v = W0[(k + 3) * 256 + n];
    } else {
      int c2 = chunk - L0_CHUNKS;
      int l = c2 >> 2, k = (c2 & 3) * KC + kk;
      const float* Ws[8] = {W1, W2, W3, W4, Wc0, Wc1, Wn0, Wn1};
      v = Ws[l][k * 256 + n];
    }
  }
  g_Wt[e] = __float2half(v);
}

// ---------------- fused kernel ----------------
struct Params {
  const float *x, *B, *W0;
  const float *b0, *b1, *b2, *b3, *b4, *bc0, *bc1, *bc2, *bn0, *bn1, *bn2;
  const float *Wc2, *Wn2;
  const int* t;
  float* out;
};

struct Ctx {
  char* smem;
  uint32_t wring32, full32, empty32;
  int tid, wm, wn, lrow, lk, grp, qp, lane;
};

// Layer-0 feature chunk (K=512, branch-free); feat buffers inside actB.
DEV void gen_feat(const Ctx& cx, int c, float tot) {
  const float* sx = (const float*)(cx.smem + OFF_SX);
  const float* sB = (const float*)(cx.smem + OFF_SB);
  __half* dst = (__half*)(cx.smem + OFF_ACTB + (c & 1) * FEAT_SZ);
  const int kk = cx.tid & 63;
  const int mb = cx.tid >> 6;
  const int kg = c * KC + kk;
  const bool issin = kg < 256;
  const int j = kg & 255;
  const float Bx = sB[j], By = sB[256 + j], Bz = sB[512 + j];
  const float a = fminf(fmaxf(tot - (float)j, 0.0f), 1.0f);
#pragma unroll
  for (int i = 0; i < 16; i++) {
    const int m = mb + i * 8;
    float px = sx[m * 4] * Bx;
    px = fmaf(sx[m * 4 + 1], By, px);
    px = fmaf(sx[m * 4 + 2], Bz, px);
    float arg = px * TWO_PI;
    float qf = rintf(arg * 0.3183098861837907f);
    float r = fmaf(qf, -3.1414794921875f, arg);
    r = fmaf(qf, -1.1315941810607910156e-4f, r);
    r = fmaf(qf, -1.9841872589410058936e-9f, r);
    float v = issin ? __sinf(r) : __cosf(r);
    if (((int)qf) & 1) v = -v;
    dst[m * WS + kk] = __float2half(v * a);
  }
}

// Software-pipelined KC=64 chunk (parity-double-buffered fragments).
DEV void chunk_mma(const Ctx& cx, uint32_t aBase, int ast, int kb, uint32_t wslot,
                   float acc[2][8][4]) {
  const uint32_t aA0 = aBase + ((cx.wm * 32 + cx.lrow) * ast + kb + cx.lk) * 2;
  const uint32_t bA0 = wslot + ((cx.wn * 64 + cx.lrow) * WS + cx.lk) * 2;
  uint32_t a0[2][4], a1[2][4], bb[2][4];
  ldsm4(a0[0], aA0);
  ldsm4(a1[0], aA0 + 16 * ast * 2);
  ldsm4(bb[0], bA0);
#pragma unroll
  for (int s = 0; s < 16; s++) {
    const int ks = s >> 2, np = s & 3;
    const int cur = s & 1, kpar = ks & 1;
    if (s + 1 < 16) {
      const int ks2 = (s + 1) >> 2, np2 = (s + 1) & 3;
      ldsm4(bb[cur ^ 1], bA0 + ks2 * 32 + np2 * (16 * WS * 2));
    }
    if (np == 2 && ks + 1 < 4) {
      ldsm4(a0[kpar ^ 1], aA0 + (ks + 1) * 32);
      ldsm4(a1[kpar ^ 1], aA0 + (ks + 1) * 32 + 16 * ast * 2);
    }
    mma16816(acc[0][2 * np],     a0[kpar], bb[cur][0], bb[cur][2]);
    mma16816(acc[0][2 * np + 1], a0[kpar], bb[cur][1], bb[cur][3]);
    mma16816(acc[1][2 * np],     a1[kpar], bb[cur][0], bb[cur][2]);
    mma16816(acc[1][2 * np + 1], a1[kpar], bb[cur][1], bb[cur][3]);
  }
}

// MODE 0: sIn -> sOut (ping-pong, 1 barrier). MODE 1/2: head dots -> outac.
template <int MODE>
__device__ __noinline__ void layerSq(const Ctx& cx, int base, const float* sbias,
                                     const __half* sIn, __half* sOut,
                                     const Params& p, int m0) {
  float* outac = (float*)(cx.smem + OFF_OUTAC);
  const uint32_t in32 = smem_u32(sIn);

  float acc[2][8][4];
#pragma unroll
  for (int a = 0; a < 2; a++)
#pragma unroll
    for (int b = 0; b < 8; b++)
#pragma unroll
      for (int d = 0; d < 4; d++) acc[a][b][d] = 0.0f;

#pragma unroll
  for (int cp = 0; cp < 2; cp++) {
    const int g0 = base + 2 * cp, g1 = g0 + 1;
    const int s0 = g0 & 1, s1 = g1 & 1;
    MBAR_WAIT(cx.full32 + s0 * 8, (g0 >> 1) & 1);
    MBAR_WAIT(cx.full32 + s1 * 8, (g1 >> 1) & 1);
    chunk_mma(cx, in32, AS, (2 * cp) * KC, cx.wring32 + s0 * CH_B, acc);
    if (cx.lane == 0) MBAR_ARRIVE(cx.empty32 + s0 * 8);
    chunk_mma(cx, in32, AS, (2 * cp + 1) * KC, cx.wring32 + s1 * CH_B, acc);
    if (cx.lane == 0) MBAR_ARRIVE(cx.empty32 + s1 * 8);
  }

  if (MODE == 0) {
#pragma unroll
    for (int mt = 0; mt < 2; mt++) {
      const int r0 = cx.wm * 32 + mt * 16 + cx.grp;
#pragma unroll
      for (int nt = 0; nt < 8; nt++) {
        const int col = cx.wn * 64 + nt * 8 + cx.qp * 2;
        float bx = sbias[col], by = sbias[col + 1];
        *(uint32_t*)(sOut + r0 * AS + col) =
            pack2(frelu(acc[mt][nt][0] + bx), frelu(acc[mt][nt][1] + by));
        *(uint32_t*)(sOut + (r0 + 8) * AS + col) =
            pack2(frelu(acc[mt][nt][2] + bx), frelu(acc[mt][nt][3] + by));
      }
    }
    barsync();  // sOut visible to all warps for next layer
  } else {
    const float* sWc2 = (const float*)(cx.smem + OFF_WC2);
    const float* sWn2 = (const float*)(cx.smem + OFF_WN2);
    constexpr int NJ = (MODE == 1) ? 3 : 1;
    float part[2][2][NJ];
#pragma unroll
    for (int a = 0; a < 2; a++)
#pragma unroll
      for (int b = 0; b < 2; b++)
#pragma unroll
        for (int j = 0; j < NJ; j++) part[a][b][j] = 0.0f;
#pragma unroll
    for (int mt = 0; mt < 2; mt++)
#pragma unroll
      for (int nt = 0; nt < 8; nt++) {
        const int col = cx.wn * 64 + nt * 8 + cx.qp * 2;
        float bx = sbias[col], by = sbias[col + 1];
        float v0 = frelu(acc[mt][nt][0] + bx), v1 = frelu(acc[mt][nt][1] + by);
        float v2 = frelu(acc[mt][nt][2] + bx), v3 = frelu(acc[mt][nt][3] + by);
#pragma unroll
        for (int j = 0; j < NJ; j++) {
          float w0 = (MODE == 1) ? sWc2[col * 3 + j] : sWn2[col];
          float w1 = (MODE == 1) ? sWc2[(col + 1) * 3 + j] : sWn2[col + 1];
          part[mt][0][j] += v0 * w0 + v1 * w1;
          part[mt][1][j] += v2 * w0 + v3 * w1;
        }
      }
#pragma unroll
    for (int mt = 0; mt < 2; mt++)
#pragma unroll
      for (int rh = 0; rh < 2; rh++)
#pragma unroll
        for (int j = 0; j < NJ; j++) {
          float v = part[mt][rh][j];
          v += __shfl_xor_sync(0xffffffffu, v, 1);
          v += __shfl_xor_sync(0xffffffffu, v, 2);
          if (cx.qp == 0)
            atomicAdd(&outac[(cx.wm * 32 + mt * 16 + rh * 8 + cx.grp) * 4 + j], v);
        }
    barsync();  // atomics visible
    if (MODE == 1) {
      if (cx.tid < 384) {
        int m = cx.tid / 3, j = cx.tid - m * 3;
        float v = outac[m * 4 + j];
        outac[m * 4 + j] = 0.0f;  // re-zero for displacement head
        p.out[(m0 + m) * 3 + j] = tanhf(v + p.bc2[j]) * 0.5f;
      }
      barsync();  // re-zero visible before next head's atomics
    } else {
      if (cx.tid < 128)
        p.out[3 * NPTS + m0 + cx.tid] = tanhf(outac[cx.tid * 4] + p.bn2[0]) * 0.1f;
    }
  }
}

__global__ void __launch_bounds__(THREADS, 1) fused_mlp(Params p) {
  extern __shared__ char smem[];
  Ctx cx;
  cx.smem = smem;
  cx.tid = threadIdx.x;
  cx.lane = cx.tid & 31;
  const int wid = cx.tid >> 5;
  cx.wm = (wid >> 2) & 3; cx.wn = wid & 3;
  cx.lrow = cx.lane & 15; cx.lk = (cx.lane >> 4) << 3;
  cx.grp = cx.lane >> 2; cx.qp = cx.lane & 3;
  cx.wring32 = smem_u32(smem + OFF_WRING);
  cx.full32 = smem_u32(smem + OFF_FULL);
  cx.empty32 = smem_u32(smem + OFF_EMPTY);

  const int m0 = blockIdx.x * MT;
  float* sx = (float*)(smem + OFF_SX);
  float* sB = (float*)(smem + OFF_SB);
  float* stail = (float*)(smem + OFF_TAIL);
  float* sb0 = (float*)(smem + OFF_BIAS);
  float* sb1 = (float*)(smem + OFF_BIAS + 1024);
  float* outac = (float*)(smem + OFF_OUTAC);
  __half* actA = (__half*)(smem + OFF_ACTA);
  __half* actB = (__half*)(smem + OFF_ACTB);

  if (cx.tid == 0) {
#pragma unroll
    for (int s = 0; s < 2; s++) {
      MBAR_INIT(cx.full32 + s * 8, 1);
      MBAR_INIT(cx.empty32 + s * 8, 16);
    }
  }
  if (cx.tid < 384) {
    int m = cx.tid / 3, d = cx.tid - m * 3;
    sx[m * 4 + d] = p.x[(m0 + m) * 3 + d];
  }
  for (int i = cx.tid; i < 768; i += THREADS) {
    sB[i] = p.B[i];
    stail[i] = p.W0[i];  // W0 rows 0..2
  }
  if (cx.tid < 256) { sb0[cx.tid] = p.b0[cx.tid]; sb1[cx.tid] = p.b1[cx.tid]; }
  if (cx.tid < CTH) outac[cx.tid] = 0.0f;
  __syncthreads();  // all 544 threads; LAST full-block barrier

  if (wid == 16) {  // ---- producer warp ----
    if (cx.lane == 0) {
      for (int i = 0; i < N_CHUNKS; i++) {
        int s = i & 1;
        MBAR_WAIT(cx.empty32 + s * 8, 1 ^ ((i >> 1) & 1));  // first 2 pass
        issue_bulk(cx.wring32 + s * CH_B, g_Wt + (size_t)i * CH_H, CH_B, cx.full32 + s * 8);
      }
    }
    return;
  }

  // ---- consumers ----
  int tbits = *p.t;
  float tval = (tbits >= 0 && tbits < (1 << 20)) ? (float)tbits : __int_as_float(tbits);
  const float tot = tval * (6000.0f / 512.0f);  // t / TAU

  // Layer 0: feat double-buffered inside actB, output -> actA
  {
    float acc[2][8][4];
#pragma unroll
    for (int a = 0; a < 2; a++)
#pragma unroll
      for (int b = 0; b < 8; b++)
#pragma unroll
        for (int d = 0; d < 4; d++) acc[a][b][d] = 0.0f;
    gen_feat(cx, 0, tot);
    const uint32_t actB32 = smem_u32(actB);
    for (int c = 0; c < L0_CHUNKS; c++) {
      barsync();  // feat buffer handoff
      const int s = c & 1;
      MBAR_WAIT(cx.full32 + s * 8, (c >> 1) & 1);
      chunk_mma(cx, actB32 + (c & 1) * FEAT_SZ, WS, 0, cx.wring32 + s * CH_B, acc);
      if (cx.lane == 0) MBAR_ARRIVE(cx.empty32 + s * 8);
      if (c + 1 < L0_CHUNKS) gen_feat(cx, c + 1, tot);
    }
    // epilogue -> actA (disjoint from actB): coord correction + bias + relu
#pragma unroll
    for (int mt = 0; mt < 2; mt++) {
      const int r0 = cx.wm * 32 + mt * 16 + cx.grp;
      const float x0a = sx[r0 * 4], x1a = sx[r0 * 4 + 1], x2a = sx[r0 * 4 + 2];
      const float x0b = sx[(r0 + 8) * 4], x1b = sx[(r0 + 8) * 4 + 1], x2b = sx[(r0 + 8) * 4 + 2];
#pragma unroll
      for (int nt = 0; nt < 8; nt++) {
        const int col = cx.wn * 64 + nt * 8 + cx.qp * 2;
        float w00 = stail[col], w01 = stail[col + 1];
        float w10 = stail[256 + col], w11 = stail[256 + col + 1];
        float w20 = stail[512 + col], w21 = stail[512 + col + 1];
        float c0 = fmaf(x0a, w00, fmaf(x1a, w10, x2a * w20));
        float c1 = fmaf(x0a, w01, fmaf(x1a, w11, x2a * w21));
        float c2 = fmaf(x0b, w00, fmaf(x1b, w10, x2b * w20));
        float c3 = fmaf(x0b, w01, fmaf(x1b, w11, x2b * w21));
        float bx = sb0[col], by = sb0[col + 1];
        *(uint32_t*)(actA + r0 * AS + col) =
            pack2(frelu(acc[mt][nt][0] + c0 + bx), frelu(acc[mt][nt][1] + c1 + by));
        *(uint32_t*)(actA + (r0 + 8) * AS + col) =
            pack2(frelu(acc[mt][nt][2] + c2 + bx), frelu(acc[mt][nt][3] + c3 + by));
      }
    }
    barsync();
  }

  // overlay head-final weights (sx/sB dead after L0 epilogue used sx... sx read done)
  {
    float* sWc2 = (float*)(smem + OFF_WC2);
    float* sWn2 = (float*)(smem + OFF_WN2);
    for (int i = cx.tid; i < 768; i += CTH) sWc2[i] = p.Wc2[i];
    if (cx.tid < 256) sWn2[cx.tid] = p.Wn2[cx.tid];
  }

  if (cx.tid < 256) sb0[cx.tid] = p.b2[cx.tid];
  layerSq<0>(cx,  8, sb1, actA, actB, p, m0);  // l1 (b1)
  if (cx.tid < 256) sb1[cx.tid] = p.b3[cx.tid];
  layerSq<0>(cx, 12, sb0, actB, actA, p, m0);  // l2 (b2)
  if (cx.tid < 256) sb0[cx.tid] = p.b4[cx.tid];
  layerSq<0>(cx, 16, sb1, actA, actB, p, m0);  // l3 (b3)
  if (cx.tid < 256) sb1[cx.tid] = p.bc0[cx.tid];
  layerSq<0>(cx, 20, sb0, actB, actA, p, m0);  // l4 (b4) -> h in actA
  if (cx.tid < 256) sb0[cx.tid] = p.bc1[cx.tid];
  layerSq<0>(cx, 24, sb1, actA, actB, p, m0);  // l5 (bc0)
  if (cx.tid < 256) sb1[cx.tid] = p.bn0[cx.tid];
  layerSq<1>(cx, 28, sb0, actB, nullptr, p, m0);  // l6 (bc1) color head
  if (cx.tid < 256) sb0[cx.tid] = p.bn1[cx.tid];
  layerSq<0>(cx, 32, sb1, actA, actB, p, m0);  // l7 (bn0), h intact in actA
  layerSq<2>(cx, 36, sb0, actB, nullptr, p, m0);  // l8 (bn1) displacement head
}

extern "C" void kernel_launch(void* const* d_in, const int* in_sizes, int n_in,
                              void* d_out, int out_size) {
  int i = 0;
  const float* x = (const float*)d_in[i++];
  const float* B = (const float*)d_in[i++];
  const void* tp = nullptr;
  if (in_sizes[2] == 1) tp = d_in[i++];  // dict order: t at index 2
  const float *W[11], *bias[11];
  for (int j = 0; j < 11; j++) {
    W[j] = (const float*)d_in[i++];
    bias[j] = (const float*)d_in[i++];
  }
  if (!tp && i < n_in) tp = d_in[i++];

  cudaFuncSetAttribute(fused_mlp, cudaFuncAttributeMaxDynamicSharedMemorySize, SMEM_BYTES);

  constexpr int TOTAL = N_CHUNKS * CH_H;
  prep_weights<<<(TOTAL + 255) / 256, 256>>>(W[0], W[1], W[2], W[3], W[4],
                                             W[5], W[6], W[8], W[9]);

  Params p;
  p.x = x; p.B = B; p.W0 = W[0];
  p.b0 = bias[0]; p.b1 = bias[1]; p.b2 = bias[2]; p.b3 = bias[3]; p.b4 = bias[4];
  p.bc0 = bias[5]; p.bc1 = bias[6]; p.bc2 = bias[7];
  p.bn0 = bias[8]; p.bn1 = bias[9]; p.bn2 = bias[10];
  p.Wc2 = W[7]; p.Wn2 = W[10];
  p.t = (const int*)tp;
  p.out = (float*)d_out;

  fused_mlp<<<NPTS / MT, THREADS, SMEM_BYTES>>>(p);
}

// round 16
// speedup vs baseline: 1.1746x; 1.0024x over previous
#include <cuda_runtime.h>
#include <cuda_fp16.h>
#include <cstdint>

#define DEV __device__ __forceinline__

namespace {
constexpr int NPTS = 131072;
constexpr int MT = 128;
constexpr int THREADS = 544;  // 16 compute warps (4 groups of 4) + 1 producer
constexpr int CTH = 512;
constexpr int KC = 64;
constexpr int AS = 264;       // activation row stride (halves)
constexpr int WS = 72;        // weight/feat row stride (halves)
constexpr float TWO_PI = 6.2831853071795864769f;

constexpr int CH_H = 256 * WS;       // 18432 halves per chunk
constexpr uint32_t CH_B = CH_H * 2;  // 36864 B
constexpr int L0_CHUNKS = 8;         // K0=512 (sin/cos; coords in epilogue)
constexpr int N_CHUNKS = L0_CHUNKS + 32;  // 40

// SMEM map (bytes)
constexpr int OFF_ACTA  = 0;                 // 67584
constexpr int OFF_ACTB  = 67584;             // 67584 (L0 feat buffers live here)
constexpr int FEAT_SZ   = 128 * WS * 2;      // 18432
constexpr int OFF_WRING = 135168;            // 2 * 36864 = 73728
constexpr int OFF_UNION = 208896;            // L0: sx+sB | heads: Wc2+Wn2
constexpr int OFF_SX    = OFF_UNION;         // 2048
constexpr int OFF_SB    = OFF_UNION + 2048;  // 3072
constexpr int OFF_WC2   = OFF_UNION;         // 3072 (overlay after L0)
constexpr int OFF_WN2   = OFF_UNION + 3072;  // 1024
constexpr int OFF_TAIL  = 214016;            // 3072 (W0 rows 0..2)
constexpr int OFF_BIAS  = 217088;            // 4 groups x 2 slots x 256 floats = 8192
constexpr int OFF_OUTAC = 225280;            // 2048
constexpr int OFF_FULL  = 227328;            // 2 x 8
constexpr int OFF_EMPTY = 227344;            // 2 x 8
constexpr int SMEM_BYTES = 227392;
}

__device__ __half g_Wt[(size_t)N_CHUNKS * CH_H];

// ---------------- helpers ----------------
DEV uint32_t smem_u32(const void* p) {
  uint32_t a;
  asm("{ .reg .u64 t; cvta.to.shared.u64 t, %1; cvt.u32.u64 %0, t; }" : "=r"(a) : "l"(p));
  return a;
}
#define MBAR_INIT(mb, c) \
  asm volatile("mbarrier.init.shared.b64 [%0], %1;" :: "r"(mb), "r"(c) : "memory")
#define MBAR_ARRIVE(mb) \
  asm volatile("mbarrier.arrive.shared.b64 _, [%0];" :: "r"(mb) : "memory")
#define MBAR_WAIT(mb, ph) do {                                                        \
  uint32_t _m = (mb), _p = (uint32_t)(ph), _d;                                        \
  asm volatile("{ .reg .pred p; mbarrier.try_wait.parity.acquire.cta.shared::cta.b64 p, [%1], %2; selp.b32 %0,1,0,p; }" \
               : "=r"(_d) : "r"(_m), "r"(_p) : "memory");                             \
  if (!_d) {                                                                          \
    asm volatile("{ .reg .pred P1; WL%=: mbarrier.try_wait.parity.acquire.cta.shared::cta.b64 P1, [%0], %1, 0x989680; @P1 bra.uni WD%=; bra.uni WL%=; WD%=: }" \
                 :: "r"(_m), "r"(_p) : "memory");                                     \
  }                                                                                   \
} while (0)

DEV void barsync_all() { asm volatile("bar.sync 1, 512;" ::: "memory"); }
DEV void grpbar(int wm) { asm volatile("bar.sync %0, 128;" :: "r"(2 + wm) : "memory"); }

DEV void issue_bulk(uint32_t dst32, const void* src, uint32_t nbytes, uint32_t mbar) {
  asm volatile("mbarrier.arrive.expect_tx.shared.b64 _, [%0], %1;"
               :: "r"(mbar), "r"(nbytes) : "memory");
  asm volatile(
      "cp.async.bulk.shared::cta.global.mbarrier::complete_tx::bytes [%0], [%1], %2, [%3];"
      :: "r"(dst32), "l"(src), "r"(nbytes), "r"(mbar) : "memory");
}

DEV void ldsm4(uint32_t* r, uint32_t addr) {
  asm volatile("ldmatrix.sync.aligned.m8n8.x4.shared.b16 {%0,%1,%2,%3}, [%4];"
               : "=r"(r[0]), "=r"(r[1]), "=r"(r[2]), "=r"(r[3]) : "r"(addr));
}
DEV void mma16816(float* d, const uint32_t* a, uint32_t b0, uint32_t b1) {
  asm volatile(
      "mma.sync.aligned.m16n8k16.row.col.f32.f16.f16.f32 "
      "{%0,%1,%2,%3}, {%4,%5,%6,%7}, {%8,%9}, {%0,%1,%2,%3};\n"
      : "+f"(d[0]), "+f"(d[1]), "+f"(d[2]), "+f"(d[3])
      : "r"(a[0]), "r"(a[1]), "r"(a[2]), "r"(a[3]), "r"(b0), "r"(b1));
}
DEV float frelu(float v) { return fmaxf(v, 0.0f); }
DEV uint32_t pack2(float a, float b) {
  __half2 h = __floats2half2_rn(a, b);
  return *reinterpret_cast<uint32_t*>(&h);
}

// ---------------- prep ----------------
__global__ void prep_weights(const float* W0, const float* W1, const float* W2,
                             const float* W3, const float* W4, const float* Wc0,
                             const float* Wc1, const float* Wn0, const float* Wn1) {
  int e = blockIdx.x * blockDim.x + threadIdx.x;
  constexpr int TOTAL = N_CHUNKS * CH_H;
  if (e >= TOTAL) return;
  int chunk = e / CH_H, r = e % CH_H, n = r / WS, kk = r % WS;
  float v = 0.0f;
  if (kk < KC) {
    if (chunk < L0_CHUNKS) {
      int k = chunk * KC + kk;
      v = W0[(k + 3) * 256 + n];
    } else {
      int c2 = chunk - L0_CHUNKS;
      int l = c2 >> 2, k = (c2 & 3) * KC + kk;
      const float* Ws[8] = {W1, W2, W3, W4, Wc0, Wc1, Wn0, Wn1};
      v = Ws[l][k * 256 + n];
    }
  }
  g_Wt[e] = __float2half(v);
}

// ---------------- fused kernel ----------------
struct Params {
  const float *x, *B, *W0;
  const float *b0, *b1, *b2, *b3, *b4, *bc0, *bc1, *bc2, *bn0, *bn1, *bn2;
  const float *Wc2, *Wn2;
  const int* t;
  float* out;
};

struct Ctx {
  char* smem;
  uint32_t wring32, full32, empty32;
  int tid, wm, wn, lrow, lk, grp, qp, lane;
};

DEV float* gbias_ptr(const Ctx& cx, int slot) {
  return (float*)(cx.smem + OFF_BIAS) + (cx.wm * 2 + slot) * 256;
}
// Group-local staging of a 256-float bias into gb[wm][slot]. Ordered vs reads by grpbar.
DEV void stage_bias(const Ctx& cx, int slot, const float* src) {
  const int lt = cx.tid & 127;
  float2 v = ((const float2*)src)[lt];
  ((float2*)gbias_ptr(cx, slot))[lt] = v;
}

// Layer-0 feature chunk (K=512, branch-free); feat buffers inside actB.
DEV void gen_feat(const Ctx& cx, int c, float tot) {
  const float* sx = (const float*)(cx.smem + OFF_SX);
  const float* sB = (const float*)(cx.smem + OFF_SB);
  __half* dst = (__half*)(cx.smem + OFF_ACTB + (c & 1) * FEAT_SZ);
  const int kk = cx.tid & 63;
  const int mb = cx.tid >> 6;
  const int kg = c * KC + kk;
  const bool issin = kg < 256;
  const int j = kg & 255;
  const float Bx = sB[j], By = sB[256 + j], Bz = sB[512 + j];
  const float a = fminf(fmaxf(tot - (float)j, 0.0f), 1.0f);
#pragma unroll
  for (int i = 0; i < 16; i++) {
    const int m = mb + i * 8;
    float px = sx[m * 4] * Bx;
    px = fmaf(sx[m * 4 + 1], By, px);
    px = fmaf(sx[m * 4 + 2], Bz, px);
    float arg = px * TWO_PI;
    float qf = rintf(arg * 0.3183098861837907f);
    float r = fmaf(qf, -3.1414794921875f, arg);
    r = fmaf(qf, -1.1315941810607910156e-4f, r);
    r = fmaf(qf, -1.9841872589410058936e-9f, r);
    float v = issin ? __sinf(r) : __cosf(r);
    if (((int)qf) & 1) v = -v;
    dst[m * WS + kk] = __float2half(v * a);
  }
}

// Software-pipelined KC=64 chunk (parity-double-buffered fragments).
DEV void chunk_mma(const Ctx& cx, uint32_t aBase, int ast, int kb, uint32_t wslot,
                   float acc[2][8][4]) {
  const uint32_t aA0 = aBase + ((cx.wm * 32 + cx.lrow) * ast + kb + cx.lk) * 2;
  const uint32_t bA0 = wslot + ((cx.wn * 64 + cx.lrow) * WS + cx.lk) * 2;
  uint32_t a0[2][4], a1[2][4], bb[2][4];
  ldsm4(a0[0], aA0);
  ldsm4(a1[0], aA0 + 16 * ast * 2);
  ldsm4(bb[0], bA0);
#pragma unroll
  for (int s = 0; s < 16; s++) {
    const int ks = s >> 2, np = s & 3;
    const int cur = s & 1, kpar = ks & 1;
    if (s + 1 < 16) {
      const int ks2 = (s + 1) >> 2, np2 = (s + 1) & 3;
      ldsm4(bb[cur ^ 1], bA0 + ks2 * 32 + np2 * (16 * WS * 2));
    }
    if (np == 2 && ks + 1 < 4) {
      ldsm4(a0[kpar ^ 1], aA0 + (ks + 1) * 32);
      ldsm4(a1[kpar ^ 1], aA0 + (ks + 1) * 32 + 16 * ast * 2);
    }
    mma16816(acc[0][2 * np],     a0[kpar], bb[cur][0], bb[cur][2]);
    mma16816(acc[0][2 * np + 1], a0[kpar], bb[cur][1], bb[cur][3]);
    mma16816(acc[1][2 * np],     a1[kpar], bb[cur][0], bb[cur][2]);
    mma16816(acc[1][2 * np + 1], a1[kpar], bb[cur][1], bb[cur][3]);
  }
}

// MODE 0: sIn -> sOut (ping-pong, group-scoped sync). MODE 1/2: head dots.
template <int MODE>
__device__ __noinline__ void layerSq(const Ctx& cx, int base, int bslot,
                                     const __half* sIn, __half* sOut,
                                     const Params& p, int m0) {
  float* outac = (float*)(cx.smem + OFF_OUTAC);
  const float* sbias = gbias_ptr(cx, bslot);
  const uint32_t in32 = smem_u32(sIn);

  float acc[2][8][4];
#pragma unroll
  for (int a = 0; a < 2; a++)
#pragma unroll
    for (int b = 0; b < 8; b++)
#pragma unroll
      for (int d = 0; d < 4; d++) acc[a][b][d] = 0.0f;

#pragma unroll
  for (int cp = 0; cp < 2; cp++) {
    const int g0 = base + 2 * cp, g1 = g0 + 1;
    const int s0 = g0 & 1, s1 = g1 & 1;
    MBAR_WAIT(cx.full32 + s0 * 8, (g0 >> 1) & 1);
    MBAR_WAIT(cx.full32 + s1 * 8, (g1 >> 1) & 1);
    chunk_mma(cx, in32, AS, (2 * cp) * KC, cx.wring32 + s0 * CH_B, acc);
    if (cx.lane == 0) MBAR_ARRIVE(cx.empty32 + s0 * 8);
    chunk_mma(cx, in32, AS, (2 * cp + 1) * KC, cx.wring32 + s1 * CH_B, acc);
    if (cx.lane == 0) MBAR_ARRIVE(cx.empty32 + s1 * 8);
  }

  if (MODE == 0) {
#pragma unroll
    for (int mt = 0; mt < 2; mt++) {
      const int r0 = cx.wm * 32 + mt * 16 + cx.grp;
#pragma unroll
      for (int nt = 0; nt < 8; nt++) {
        const int col = cx.wn * 64 + nt * 8 + cx.qp * 2;
        float bx = sbias[col], by = sbias[col + 1];
        *(uint32_t*)(sOut + r0 * AS + col) =
            pack2(frelu(acc[mt][nt][0] + bx), frelu(acc[mt][nt][1] + by));
        *(uint32_t*)(sOut + (r0 + 8) * AS + col) =
            pack2(frelu(acc[mt][nt][2] + bx), frelu(acc[mt][nt][3] + by));
      }
    }
    grpbar(cx.wm);  // band handoff within group
  } else {
    const float* sWc2 = (const float*)(cx.smem + OFF_WC2);
    const float* sWn2 = (const float*)(cx.smem + OFF_WN2);
    constexpr int NJ = (MODE == 1) ? 3 : 1;
    float part[2][2][NJ];
#pragma unroll
    for (int a = 0; a < 2; a++)
#pragma unroll
      for (int b = 0; b < 2; b++)
#pragma unroll
        for (int j = 0; j < NJ; j++) part[a][b][j] = 0.0f;
#pragma unroll
    for (int mt = 0; mt < 2; mt++)
#pragma unroll
      for (int nt = 0; nt < 8; nt++) {
        const int col = cx.wn * 64 + nt * 8 + cx.qp * 2;
        float bx = sbias[col], by = sbias[col + 1];
        float v0 = frelu(acc[mt][nt][0] + bx), v1 = frelu(acc[mt][nt][1] + by);
        float v2 = frelu(acc[mt][nt][2] + bx), v3 = frelu(acc[mt][nt][3] + by);
#pragma unroll
        for (int j = 0; j < NJ; j++) {
          float w0 = (MODE == 1) ? sWc2[col * 3 + j] : sWn2[col];
          float w1 = (MODE == 1) ? sWc2[(col + 1) * 3 + j] : sWn2[col + 1];
          part[mt][0][j] += v0 * w0 + v1 * w1;
          part[mt][1][j] += v2 * w0 + v3 * w1;
        }
      }
#pragma unroll
    for (int mt = 0; mt < 2; mt++)
#pragma unroll
      for (int rh = 0; rh < 2; rh++)
#pragma unroll
        for (int j = 0; j < NJ; j++) {
          float v = part[mt][rh][j];
          v += __shfl_xor_sync(0xffffffffu, v, 1);
          v += __shfl_xor_sync(0xffffffffu, v, 2);
          if (cx.qp == 0)
            atomicAdd(&outac[(cx.wm * 32 + mt * 16 + rh * 8 + cx.grp) * 4 + j], v);
        }
    grpbar(cx.wm);  // atomics visible within group (band-local)
    const int lt = cx.tid & 127;
    if (MODE == 1) {
      if (lt < 96) {
        int ml = lt / 3, j = lt - ml * 3;
        int row = cx.wm * 32 + ml;
        float v = outac[row * 4 + j];
        outac[row * 4 + j] = 0.0f;  // re-zero for displacement head
        p.out[(m0 + row) * 3 + j] = tanhf(v + p.bc2[j]) * 0.5f;
      }
      grpbar(cx.wm);  // re-zero visible before this group's l8 atomics
    } else {
      if (lt < 32) {
        int row = cx.wm * 32 + lt;
        p.out[3 * NPTS + m0 + row] = tanhf(outac[row * 4] + p.bn2[0]) * 0.1f;
      }
    }
  }
}

__global__ void __launch_bounds__(THREADS, 1) fused_mlp(Params p) {
  extern __shared__ char smem[];
  Ctx cx;
  cx.smem = smem;
  cx.tid = threadIdx.x;
  cx.lane = cx.tid & 31;
  const int wid = cx.tid >> 5;
  cx.wm = (wid >> 2) & 3; cx.wn = wid & 3;
  cx.lrow = cx.lane & 15; cx.lk = (cx.lane >> 4) << 3;
  cx.grp = cx.lane >> 2; cx.qp = cx.lane & 3;
  cx.wring32 = smem_u32(smem + OFF_WRING);
  cx.full32 = smem_u32(smem + OFF_FULL);
  cx.empty32 = smem_u32(smem + OFF_EMPTY);

  const int m0 = blockIdx.x * MT;
  float* sx = (float*)(smem + OFF_SX);
  float* sB = (float*)(smem + OFF_SB);
  float* stail = (float*)(smem + OFF_TAIL);
  float* outac = (float*)(smem + OFF_OUTAC);
  __half* actA = (__half*)(smem + OFF_ACTA);
  __half* actB = (__half*)(smem + OFF_ACTB);

  if (cx.tid == 0) {
#pragma unroll
    for (int s = 0; s < 2; s++) {
      MBAR_INIT(cx.full32 + s * 8, 1);
      MBAR_INIT(cx.empty32 + s * 8, 16);
    }
  }
  if (cx.tid < 384) {
    int m = cx.tid / 3, d = cx.tid - m * 3;
    sx[m * 4 + d] = p.x[(m0 + m) * 3 + d];
  }
  for (int i = cx.tid; i < 768; i += THREADS) {
    sB[i] = p.B[i];
    stail[i] = p.W0[i];  // W0 rows 0..2
  }
  if (cx.tid < CTH) {
    stage_bias(cx, 0, p.b0);
    stage_bias(cx, 1, p.b1);
    outac[cx.tid] = 0.0f;
  }
  __syncthreads();  // all 544 threads

  if (wid == 16) {  // ---- producer warp ----
    if (cx.lane == 0) {
      for (int i = 0; i < N_CHUNKS; i++) {
        int s = i & 1;
        MBAR_WAIT(cx.empty32 + s * 8, 1 ^ ((i >> 1) & 1));  // first 2 pass
        issue_bulk(cx.wring32 + s * CH_B, g_Wt + (size_t)i * CH_H, CH_B, cx.full32 + s * 8);
      }
    }
    return;
  }

  // ---- consumers ----
  int tbits = *p.t;
  float tval = (tbits >= 0 && tbits < (1 << 20)) ? (float)tbits : __int_as_float(tbits);
  const float tot = tval * (6000.0f / 512.0f);  // t / TAU

  // Layer 0: feat double-buffered inside actB, output -> actA (full-CTA barriers)
  {
    float acc[2][8][4];
#pragma unroll
    for (int a = 0; a < 2; a++)
#pragma unroll
      for (int b = 0; b < 8; b++)
#pragma unroll
        for (int d = 0; d < 4; d++) acc[a][b][d] = 0.0f;
    gen_feat(cx, 0, tot);
    const uint32_t actB32 = smem_u32(actB);
    for (int c = 0; c < L0_CHUNKS; c++) {
      barsync_all();  // feat buffer handoff
      const int s = c & 1;
      MBAR_WAIT(cx.full32 + s * 8, (c >> 1) & 1);
      chunk_mma(cx, actB32 + (c & 1) * FEAT_SZ, WS, 0, cx.wring32 + s * CH_B, acc);
      if (cx.lane == 0) MBAR_ARRIVE(cx.empty32 + s * 8);
      if (c + 1 < L0_CHUNKS) gen_feat(cx, c + 1, tot);
    }
    // epilogue -> actA: coord correction + bias(b0, slot 0) + relu
    const float* sb0g = gbias_ptr(cx, 0);
#pragma unroll
    for (int mt = 0; mt < 2; mt++) {
      const int r0 = cx.wm * 32 + mt * 16 + cx.grp;
      const float x0a = sx[r0 * 4], x1a = sx[r0 * 4 + 1], x2a = sx[r0 * 4 + 2];
      const float x0b = sx[(r0 + 8) * 4], x1b = sx[(r0 + 8) * 4 + 1], x2b = sx[(r0 + 8) * 4 + 2];
#pragma unroll
      for (int nt = 0; nt < 8; nt++) {
        const int col = cx.wn * 64 + nt * 8 + cx.qp * 2;
        float w00 = stail[col], w01 = stail[col + 1];
        float w10 = stail[256 + col], w11 = stail[256 + col + 1];
        float w20 = stail[512 + col], w21 = stail[512 + col + 1];
        float c0 = fmaf(x0a, w00, fmaf(x1a, w10, x2a * w20));
        float c1 = fmaf(x0a, w01, fmaf(x1a, w11, x2a * w21));
        float c2 = fmaf(x0b, w00, fmaf(x1b, w10, x2b * w20));
        float c3 = fmaf(x0b, w01, fmaf(x1b, w11, x2b * w21));
        float bx = sb0g[col], by = sb0g[col + 1];
        *(uint32_t*)(actA + r0 * AS + col) =
            pack2(frelu(acc[mt][nt][0] + c0 + bx), frelu(acc[mt][nt][1] + c1 + by));
        *(uint32_t*)(actA + (r0 + 8) * AS + col) =
            pack2(frelu(acc[mt][nt][2] + c2 + bx), frelu(acc[mt][nt][3] + c3 + by));
      }
    }
    barsync_all();
  }

  // overlay head-final weights (sx/sB dead), then full barrier: all later
  // group-scoped reads of sWc2/sWn2/actA are ordered after these writes.
  {
    float* sWc2 = (float*)(smem + OFF_WC2);
    float* sWn2 = (float*)(smem + OFF_WN2);
    for (int i = cx.tid; i < 768; i += CTH) sWc2[i] = p.Wc2[i];
    if (cx.tid < 256) sWn2[cx.tid] = p.Wn2[cx.tid];
  }
  barsync_all();

  // Square layers: group-scoped sync; bias staged one layer ahead per group.
  stage_bias(cx, 0, p.b2);
  layerSq<0>(cx,  8, 1, actA, actB, p, m0);  // l1 (b1)
  stage_bias(cx, 1, p.b3);
  layerSq<0>(cx, 12, 0, actB, actA, p, m0);  // l2 (b2)
  stage_bias(cx, 0, p.b4);
  layerSq<0>(cx, 16, 1, actA, actB, p, m0);  // l3 (b3)
  stage_bias(cx, 1, p.bc0);
  layerSq<0>(cx, 20, 0, actB, actA, p, m0);  // l4 (b4) -> h in actA
  stage_bias(cx, 0, p.bc1);
  layerSq<0>(cx, 24, 1, actA, actB, p, m0);  // l5 (bc0)
  stage_bias(cx, 1, p.bn0);
  layerSq<1>(cx, 28, 0, actB, nullptr, p, m0);  // l6 (bc1) color head
  stage_bias(cx, 0, p.bn1);
  layerSq<0>(cx, 32, 1, actA, actB, p, m0);  // l7 (bn0), h intact in actA
  layerSq<2>(cx, 36, 0, actB, nullptr, p, m0);  // l8 (bn1) displacement head
}

extern "C" void kernel_launch(void* const* d_in, const int* in_sizes, int n_in,
                              void* d_out, int out_size) {
  int i = 0;
  const float* x = (const float*)d_in[i++];
  const float* B = (const float*)d_in[i++];
  const void* tp = nullptr;
  if (in_sizes[2] == 1) tp = d_in[i++];  // dict order: t at index 2
  const float *W[11], *bias[11];
  for (int j = 0; j < 11; j++) {
    W[j] = (const float*)d_in[i++];
    bias[j] = (const float*)d_in[i++];
  }
  if (!tp && i < n_in) tp = d_in[i++];

  cudaFuncSetAttribute(fused_mlp, cudaFuncAttributeMaxDynamicSharedMemorySize, SMEM_BYTES);

  constexpr int TOTAL = N_CHUNKS * CH_H;
  prep_weights<<<(TOTAL + 255) / 256, 256>>>(W[0], W[1], W[2], W[3], W[4],
                                             W[5], W[6], W[8], W[9]);

  Params p;
  p.x = x; p.B = B; p.W0 = W[0];
  p.b0 = bias[0]; p.b1 = bias[1]; p.b2 = bias[2]; p.b3 = bias[3]; p.b4 = bias[4];
  p.bc0 = bias[5]; p.bc1 = bias[6]; p.bc2 = bias[7];
  p.bn0 = bias[8]; p.bn1 = bias[9]; p.bn2 = bias[10];
  p.Wc2 = W[7]; p.Wn2 = W[10];
  p.t = (const int*)tp;
  p.out = (float*)d_out;

  fused_mlp<<<NPTS / MT, THREADS, SMEM_BYTES>>>(p);
}

// round 17
// speedup vs baseline: 1.2518x; 1.0657x over previous
#include <cuda_runtime.h>
#include <cuda_fp16.h>
#include <cstdint>

#define DEV __device__ __forceinline__

namespace {
constexpr int NPTS = 131072;
constexpr int MT = 128;
constexpr int THREADS = 544;  // 16 compute warps (4 groups of 4) + 1 producer
constexpr int CTH = 512;
constexpr int KC = 64;
constexpr int AS = 264;       // activation row stride (halves)
constexpr int WS = 72;        // weight/feat row stride (halves)
constexpr float TWO_PI = 6.2831853071795864769f;

constexpr int CH_H = 256 * WS;       // 18432 halves per chunk
constexpr uint32_t CH_B = CH_H * 2;  // 36864 B
constexpr int L0_CHUNKS = 8;         // K0=512 (interleaved sin/cos; coords in epilogue)
constexpr int N_CHUNKS = L0_CHUNKS + 32;  // 40

// SMEM map (bytes)
constexpr int OFF_ACTA  = 0;                 // 67584
constexpr int OFF_ACTB  = 67584;             // 67584 (L0 feat buffers live here)
constexpr int FEAT_SZ   = 128 * WS * 2;      // 18432
constexpr int OFF_WRING = 135168;            // 2 * 36864 = 73728
constexpr int OFF_UNION = 208896;            // L0: sx+sB | heads: Wc2+Wn2
constexpr int OFF_SX    = OFF_UNION;         // 2048
constexpr int OFF_SB    = OFF_UNION + 2048;  // 3072
constexpr int OFF_WC2   = OFF_UNION;         // 3072 (overlay after L0)
constexpr int OFF_WN2   = OFF_UNION + 3072;  // 1024
constexpr int OFF_TAIL  = 214016;            // 3072 (W0 rows 0..2)
constexpr int OFF_BIAS  = 217088;            // 4 groups x 2 slots x 256 floats = 8192
constexpr int OFF_OUTAC = 225280;            // 2048
constexpr int OFF_FULL  = 227328;            // 2 x 8
constexpr int OFF_EMPTY = 227344;            // 2 x 8
constexpr int SMEM_BYTES = 227392;
}

__device__ __half g_Wt[(size_t)N_CHUNKS * CH_H];

// ---------------- helpers ----------------
DEV uint32_t smem_u32(const void* p) {
  uint32_t a;
  asm("{ .reg .u64 t; cvta.to.shared.u64 t, %1; cvt.u32.u64 %0, t; }" : "=r"(a) : "l"(p));
  return a;
}
#define MBAR_INIT(mb, c) \
  asm volatile("mbarrier.init.shared.b64 [%0], %1;" :: "r"(mb), "r"(c) : "memory")
#define MBAR_ARRIVE(mb) \
  asm volatile("mbarrier.arrive.shared.b64 _, [%0];" :: "r"(mb) : "memory")
#define MBAR_WAIT(mb, ph) do {                                                        \
  uint32_t _m = (mb), _p = (uint32_t)(ph), _d;                                        \
  asm volatile("{ .reg .pred p; mbarrier.try_wait.parity.acquire.cta.shared::cta.b64 p, [%1], %2; selp.b32 %0,1,0,p; }" \
               : "=r"(_d) : "r"(_m), "r"(_p) : "memory");                             \
  if (!_d) {                                                                          \
    asm volatile("{ .reg .pred P1; WL%=: mbarrier.try_wait.parity.acquire.cta.shared::cta.b64 P1, [%0], %1, 0x989680; @P1 bra.uni WD%=; bra.uni WL%=; WD%=: }" \
                 :: "r"(_m), "r"(_p) : "memory");                                     \
  }                                                                                   \
} while (0)

DEV void barsync_all() { asm volatile("bar.sync 1, 512;" ::: "memory"); }
DEV void grpbar(int wm) { asm volatile("bar.sync %0, 128;" :: "r"(2 + wm) : "memory"); }

DEV void issue_bulk(uint32_t dst32, const void* src, uint32_t nbytes, uint32_t mbar) {
  asm volatile("mbarrier.arrive.expect_tx.shared.b64 _, [%0], %1;"
               :: "r"(mbar), "r"(nbytes) : "memory");
  asm volatile(
      "cp.async.bulk.shared::cta.global.mbarrier::complete_tx::bytes [%0], [%1], %2, [%3];"
      :: "r"(dst32), "l"(src), "r"(nbytes), "r"(mbar) : "memory");
}

DEV void ldsm4(uint32_t* r, uint32_t addr) {
  asm volatile("ldmatrix.sync.aligned.m8n8.x4.shared.b16 {%0,%1,%2,%3}, [%4];"
               : "=r"(r[0]), "=r"(r[1]), "=r"(r[2]), "=r"(r[3]) : "r"(addr));
}
DEV void mma16816(float* d, const uint32_t* a, uint32_t b0, uint32_t b1) {
  asm volatile(
      "mma.sync.aligned.m16n8k16.row.col.f32.f16.f16.f32 "
      "{%0,%1,%2,%3}, {%4,%5,%6,%7}, {%8,%9}, {%0,%1,%2,%3};\n"
      : "+f"(d[0]), "+f"(d[1]), "+f"(d[2]), "+f"(d[3])
      : "r"(a[0]), "r"(a[1]), "r"(a[2]), "r"(a[3]), "r"(b0), "r"(b1));
}
DEV float frelu(float v) { return fmaxf(v, 0.0f); }
DEV uint32_t pack2(float a, float b) {
  __half2 h = __floats2half2_rn(a, b);
  return *reinterpret_cast<uint32_t*>(&h);
}

// ---------------- prep ----------------
// L0 K-order is interleaved: k' = 2j -> sin(j) (W0 row 3+j), k' = 2j+1 -> cos(j)
// (W0 row 259+j). gen_feat produces features in the same order.
__global__ void prep_weights(const float* W0, const float* W1, const float* W2,
                             const float* W3, const float* W4, const float* Wc0,
                             const float* Wc1, const float* Wn0, const float* Wn1) {
  int e = blockIdx.x * blockDim.x + threadIdx.x;
  constexpr int TOTAL = N_CHUNKS * CH_H;
  if (e >= TOTAL) return;
  int chunk = e / CH_H, r = e % CH_H, n = r / WS, kk = r % WS;
  float v = 0.0f;
  if (kk < KC) {
    if (chunk < L0_CHUNKS) {
      int kp = chunk * KC + kk;           // 0..511 interleaved feature index
      int j = kp >> 1;
      int row = 3 + j + 256 * (kp & 1);   // sin -> 3+j, cos -> 259+j
      v = W0[row * 256 + n];
    } else {
      int c2 = chunk - L0_CHUNKS;
      int l = c2 >> 2, k = (c2 & 3) * KC + kk;
      const float* Ws[8] = {W1, W2, W3, W4, Wc0, Wc1, Wn0, Wn1};
      v = Ws[l][k * 256 + n];
    }
  }
  g_Wt[e] = __float2half(v);
}

// ---------------- fused kernel ----------------
struct Params {
  const float *x, *B, *W0;
  const float *b0, *b1, *b2, *b3, *b4, *bc0, *bc1, *bc2, *bn0, *bn1, *bn2;
  const float *Wc2, *Wn2;
  const int* t;
  float* out;
};

struct Ctx {
  char* smem;
  uint32_t wring32, full32, empty32;
  int tid, wm, wn, lrow, lk, grp, qp, lane;
};

DEV float* gbias_ptr(const Ctx& cx, int slot) {
  return (float*)(cx.smem + OFF_BIAS) + (cx.wm * 2 + slot) * 256;
}
DEV void stage_bias(const Ctx& cx, int slot, const float* src) {
  const int lt = cx.tid & 127;
  float2 v = ((const float2*)src)[lt];
  ((float2*)gbias_ptr(cx, slot))[lt] = v;
}

// Layer-0 feature chunk: one thread = one j, computes BOTH sin and cos of the
// same projection (interleaved K layout), one packed 32-bit store per row.
DEV void gen_feat(const Ctx& cx, int c, float tot) {
  const float* sx = (const float*)(cx.smem + OFF_SX);
  const float* sB = (const float*)(cx.smem + OFF_SB);
  __half* dst = (__half*)(cx.smem + OFF_ACTB + (c & 1) * FEAT_SZ);
  const int jj = cx.tid & 31;       // local j within chunk (32 pairs = 64 K cols)
  const int mb = cx.tid >> 5;       // 0..15; m = mb + i*16
  const int j = c * 32 + jj;        // 0..255
  const float Bx = sB[j], By = sB[256 + j], Bz = sB[512 + j];
  const float a = fminf(fmaxf(tot - (float)j, 0.0f), 1.0f);
#pragma unroll
  for (int i = 0; i < 8; i++) {
    const int m = mb + i * 16;
    float px = sx[m * 4] * Bx;
    px = fmaf(sx[m * 4 + 1], By, px);
    px = fmaf(sx[m * 4 + 2], Bz, px);
    float arg = px * TWO_PI;
    float qf = rintf(arg * 0.3183098861837907f);
    float r = fmaf(qf, -3.1414794921875f, arg);
    r = fmaf(qf, -1.1315941810607910156e-4f, r);
    r = fmaf(qf, -1.9841872589410058936e-9f, r);
    float sv = __sinf(r), cv = __cosf(r);
    if (((int)qf) & 1) { sv = -sv; cv = -cv; }
    *(uint32_t*)(dst + m * WS + 2 * jj) = pack2(sv * a, cv * a);
  }
}

// Software-pipelined KC=64 chunk (parity-double-buffered fragments).
DEV void chunk_mma(const Ctx& cx, uint32_t aBase, int ast, int kb, uint32_t wslot,
                   float acc[2][8][4]) {
  const uint32_t aA0 = aBase + ((cx.wm * 32 + cx.lrow) * ast + kb + cx.lk) * 2;
  const uint32_t bA0 = wslot + ((cx.wn * 64 + cx.lrow) * WS + cx.lk) * 2;
  uint32_t a0[2][4], a1[2][4], bb[2][4];
  ldsm4(a0[0], aA0);
  ldsm4(a1[0], aA0 + 16 * ast * 2);
  ldsm4(bb[0], bA0);
#pragma unroll
  for (int s = 0; s < 16; s++) {
    const int ks = s >> 2, np = s & 3;
    const int cur = s & 1, kpar = ks & 1;
    if (s + 1 < 16) {
      const int ks2 = (s + 1) >> 2, np2 = (s + 1) & 3;
      ldsm4(bb[cur ^ 1], bA0 + ks2 * 32 + np2 * (16 * WS * 2));
    }
    if (np == 2 && ks + 1 < 4) {
      ldsm4(a0[kpar ^ 1], aA0 + (ks + 1) * 32);
      ldsm4(a1[kpar ^ 1], aA0 + (ks + 1) * 32 + 16 * ast * 2);
    }
    mma16816(acc[0][2 * np],     a0[kpar], bb[cur][0], bb[cur][2]);
    mma16816(acc[0][2 * np + 1], a0[kpar], bb[cur][1], bb[cur][3]);
    mma16816(acc[1][2 * np],     a1[kpar], bb[cur][0], bb[cur][2]);
    mma16816(acc[1][2 * np + 1], a1[kpar], bb[cur][1], bb[cur][3]);
  }
}

// MODE 0: sIn -> sOut (ping-pong, group-scoped sync). MODE 1/2: head dots.
template <int MODE>
__device__ __noinline__ void layerSq(const Ctx& cx, int base, int bslot,
                                     const __half* sIn, __half* sOut,
                                     const Params& p, int m0) {
  float* outac = (float*)(cx.smem + OFF_OUTAC);
  const float* sbias = gbias_ptr(cx, bslot);
  const uint32_t in32 = smem_u32(sIn);

  float acc[2][8][4];
#pragma unroll
  for (int a = 0; a < 2; a++)
#pragma unroll
    for (int b = 0; b < 8; b++)
#pragma unroll
      for (int d = 0; d < 4; d++) acc[a][b][d] = 0.0f;

#pragma unroll
  for (int cp = 0; cp < 2; cp++) {
    const int g0 = base + 2 * cp, g1 = g0 + 1;
    const int s0 = g0 & 1, s1 = g1 & 1;
    MBAR_WAIT(cx.full32 + s0 * 8, (g0 >> 1) & 1);
    MBAR_WAIT(cx.full32 + s1 * 8, (g1 >> 1) & 1);
    chunk_mma(cx, in32, AS, (2 * cp) * KC, cx.wring32 + s0 * CH_B, acc);
    if (cx.lane == 0) MBAR_ARRIVE(cx.empty32 + s0 * 8);
    chunk_mma(cx, in32, AS, (2 * cp + 1) * KC, cx.wring32 + s1 * CH_B, acc);
    if (cx.lane == 0) MBAR_ARRIVE(cx.empty32 + s1 * 8);
  }

  if (MODE == 0) {
#pragma unroll
    for (int mt = 0; mt < 2; mt++) {
      const int r0 = cx.wm * 32 + mt * 16 + cx.grp;
#pragma unroll
      for (int nt = 0; nt < 8; nt++) {
        const int col = cx.wn * 64 + nt * 8 + cx.qp * 2;
        float bx = sbias[col], by = sbias[col + 1];
        *(uint32_t*)(sOut + r0 * AS + col) =
            pack2(frelu(acc[mt][nt][0] + bx), frelu(acc[mt][nt][1] + by));
        *(uint32_t*)(sOut + (r0 + 8) * AS + col) =
            pack2(frelu(acc[mt][nt][2] + bx), frelu(acc[mt][nt][3] + by));
      }
    }
    grpbar(cx.wm);  // band handoff within group
  } else {
    const float* sWc2 = (const float*)(cx.smem + OFF_WC2);
    const float* sWn2 = (const float*)(cx.smem + OFF_WN2);
    constexpr int NJ = (MODE == 1) ? 3 : 1;
    float part[2][2][NJ];
#pragma unroll
    for (int a = 0; a < 2; a++)
#pragma unroll
      for (int b = 0; b < 2; b++)
#pragma unroll
        for (int j = 0; j < NJ; j++) part[a][b][j] = 0.0f;
#pragma unroll
    for (int mt = 0; mt < 2; mt++)
#pragma unroll
      for (int nt = 0; nt < 8; nt++) {
        const int col = cx.wn * 64 + nt * 8 + cx.qp * 2;
        float bx = sbias[col], by = sbias[col + 1];
        float v0 = frelu(acc[mt][nt][0] + bx), v1 = frelu(acc[mt][nt][1] + by);
        float v2 = frelu(acc[mt][nt][2] + bx), v3 = frelu(acc[mt][nt][3] + by);
#pragma unroll
        for (int j = 0; j < NJ; j++) {
          float w0 = (MODE == 1) ? sWc2[col * 3 + j] : sWn2[col];
          float w1 = (MODE == 1) ? sWc2[(col + 1) * 3 + j] : sWn2[col + 1];
          part[mt][0][j] += v0 * w0 + v1 * w1;
          part[mt][1][j] += v2 * w0 + v3 * w1;
        }
      }
#pragma unroll
    for (int mt = 0; mt < 2; mt++)
#pragma unroll
      for (int rh = 0; rh < 2; rh++)
#pragma unroll
        for (int j = 0; j < NJ; j++) {
          float v = part[mt][rh][j];
          v += __shfl_xor_sync(0xffffffffu, v, 1);
          v += __shfl_xor_sync(0xffffffffu, v, 2);
          if (cx.qp == 0)
            atomicAdd(&outac[(cx.wm * 32 + mt * 16 + rh * 8 + cx.grp) * 4 + j], v);
        }
    grpbar(cx.wm);  // atomics visible within group (band-local)
    const int lt = cx.tid & 127;
    if (MODE == 1) {
      if (lt < 96) {
        int ml = lt / 3, j = lt - ml * 3;
        int row = cx.wm * 32 + ml;
        float v = outac[row * 4 + j];
        outac[row * 4 + j] = 0.0f;  // re-zero for displacement head
        p.out[(m0 + row) * 3 + j] = tanhf(v + p.bc2[j]) * 0.5f;
      }
      grpbar(cx.wm);  // re-zero visible before this group's l8 atomics
    } else {
      if (lt < 32) {
        int row = cx.wm * 32 + lt;
        p.out[3 * NPTS + m0 + row] = tanhf(outac[row * 4] + p.bn2[0]) * 0.1f;
      }
    }
  }
}

__global__ void __launch_bounds__(THREADS, 1) fused_mlp(Params p) {
  extern __shared__ char smem[];
  Ctx cx;
  cx.smem = smem;
  cx.tid = threadIdx.x;
  cx.lane = cx.tid & 31;
  const int wid = cx.tid >> 5;
  cx.wm = (wid >> 2) & 3; cx.wn = wid & 3;
  cx.lrow = cx.lane & 15; cx.lk = (cx.lane >> 4) << 3;
  cx.grp = cx.lane >> 2; cx.qp = cx.lane & 3;
  cx.wring32 = smem_u32(smem + OFF_WRING);
  cx.full32 = smem_u32(smem + OFF_FULL);
  cx.empty32 = smem_u32(smem + OFF_EMPTY);

  const int m0 = blockIdx.x * MT;
  float* sx = (float*)(smem + OFF_SX);
  float* sB = (float*)(smem + OFF_SB);
  float* stail = (float*)(smem + OFF_TAIL);
  float* outac = (float*)(smem + OFF_OUTAC);
  __half* actA = (__half*)(smem + OFF_ACTA);
  __half* actB = (__half*)(smem + OFF_ACTB);

  if (cx.tid == 0) {
#pragma unroll
    for (int s = 0; s < 2; s++) {
      MBAR_INIT(cx.full32 + s * 8, 1);
      MBAR_INIT(cx.empty32 + s * 8, 16);
    }
  }
  if (cx.tid < 384) {
    int m = cx.tid / 3, d = cx.tid - m * 3;
    sx[m * 4 + d] = p.x[(m0 + m) * 3 + d];
  }
  for (int i = cx.tid; i < 768; i += THREADS) {
    sB[i] = p.B[i];
    stail[i] = p.W0[i];  // W0 rows 0..2
  }
  if (cx.tid < CTH) {
    stage_bias(cx, 0, p.b0);
    stage_bias(cx, 1, p.b1);
    outac[cx.tid] = 0.0f;
  }
  __syncthreads();  // all 544 threads

  if (wid == 16) {  // ---- producer warp ----
    if (cx.lane == 0) {
      for (int i = 0; i < N_CHUNKS; i++) {
        int s = i & 1;
        MBAR_WAIT(cx.empty32 + s * 8, 1 ^ ((i >> 1) & 1));  // first 2 pass
        issue_bulk(cx.wring32 + s * CH_B, g_Wt + (size_t)i * CH_H, CH_B, cx.full32 + s * 8);
      }
    }
    return;
  }

  // ---- consumers ----
  int tbits = *p.t;
  float tval = (tbits >= 0 && tbits < (1 << 20)) ? (float)tbits : __int_as_float(tbits);
  const float tot = tval * (6000.0f / 512.0f);  // t / TAU

  // Layer 0: feat double-buffered inside actB, output -> actA (full-CTA barriers)
  {
    float acc[2][8][4];
#pragma unroll
    for (int a = 0; a < 2; a++)
#pragma unroll
      for (int b = 0; b < 8; b++)
#pragma unroll
        for (int d = 0; d < 4; d++) acc[a][b][d] = 0.0f;
    gen_feat(cx, 0, tot);
    const uint32_t actB32 = smem_u32(actB);
    for (int c = 0; c < L0_CHUNKS; c++) {
      barsync_all();  // feat buffer handoff
      const int s = c & 1;
      MBAR_WAIT(cx.full32 + s * 8, (c >> 1) & 1);
      chunk_mma(cx, actB32 + (c & 1) * FEAT_SZ, WS, 0, cx.wring32 + s * CH_B, acc);
      if (cx.lane == 0) MBAR_ARRIVE(cx.empty32 + s * 8);
      if (c + 1 < L0_CHUNKS) gen_feat(cx, c + 1, tot);
    }
    // epilogue -> actA: coord correction + bias(b0, slot 0) + relu
    const float* sb0g = gbias_ptr(cx, 0);
#pragma unroll
    for (int mt = 0; mt < 2; mt++) {
      const int r0 = cx.wm * 32 + mt * 16 + cx.grp;
      const float x0a = sx[r0 * 4], x1a = sx[r0 * 4 + 1], x2a = sx[r0 * 4 + 2];
      const float x0b = sx[(r0 + 8) * 4], x1b = sx[(r0 + 8) * 4 + 1], x2b = sx[(r0 + 8) * 4 + 2];
#pragma unroll
      for (int nt = 0; nt < 8; nt++) {
        const int col = cx.wn * 64 + nt * 8 + cx.qp * 2;
        float w00 = stail[col], w01 = stail[col + 1];
        float w10 = stail[256 + col], w11 = stail[256 + col + 1];
        float w20 = stail[512 + col], w21 = stail[512 + col + 1];
        float c0 = fmaf(x0a, w00, fmaf(x1a, w10, x2a * w20));
        float c1 = fmaf(x0a, w01, fmaf(x1a, w11, x2a * w21));
        float c2 = fmaf(x0b, w00, fmaf(x1b, w10, x2b * w20));
        float c3 = fmaf(x0b, w01, fmaf(x1b, w11, x2b * w21));
        float bx = sb0g[col], by = sb0g[col + 1];
        *(uint32_t*)(actA + r0 * AS + col) =
            pack2(frelu(acc[mt][nt][0] + c0 + bx), frelu(acc[mt][nt][1] + c1 + by));
        *(uint32_t*)(actA + (r0 + 8) * AS + col) =
            pack2(frelu(acc[mt][nt][2] + c2 + bx), frelu(acc[mt][nt][3] + c3 + by));
      }
    }
    barsync_all();
  }

  // overlay head-final weights (sx/sB dead), then full barrier.
  {
    float* sWc2 = (float*)(smem + OFF_WC2);
    float* sWn2 = (float*)(smem + OFF_WN2);
    for (int i = cx.tid; i < 768; i += CTH) sWc2[i] = p.Wc2[i];
    if (cx.tid < 256) sWn2[cx.tid] = p.Wn2[cx.tid];
  }
  barsync_all();

  // Square layers: group-scoped sync; bias staged one layer ahead per group.
  stage_bias(cx, 0, p.b2);
  layerSq<0>(cx,  8, 1, actA, actB, p, m0);  // l1 (b1)
  stage_bias(cx, 1, p.b3);
  layerSq<0>(cx, 12, 0, actB, actA, p, m0);  // l2 (b2)
  stage_bias(cx, 0, p.b4);
  layerSq<0>(cx, 16, 1, actA, actB, p, m0);  // l3 (b3)
  stage_bias(cx, 1, p.bc0);
  layerSq<0>(cx, 20, 0, actB, actA, p, m0);  // l4 (b4) -> h in actA
  stage_bias(cx, 0, p.bc1);
  layerSq<0>(cx, 24, 1, actA, actB, p, m0);  // l5 (bc0)
  stage_bias(cx, 1, p.bn0);
  layerSq<1>(cx, 28, 0, actB, nullptr, p, m0);  // l6 (bc1) color head
  stage_bias(cx, 0, p.bn1);
  layerSq<0>(cx, 32, 1, actA, actB, p, m0);  // l7 (bn0), h intact in actA
  layerSq<2>(cx, 36, 0, actB, nullptr, p, m0);  // l8 (bn1) displacement head
}

extern "C" void kernel_launch(void* const* d_in, const int* in_sizes, int n_in,
                              void* d_out, int out_size) {
  int i = 0;
  const float* x = (const float*)d_in[i++];
  const float* B = (const float*)d_in[i++];
  const void* tp = nullptr;
  if (in_sizes[2] == 1) tp = d_in[i++];  // dict order: t at index 2
  const float *W[11], *bias[11];
  for (int j = 0; j < 11; j++) {
    W[j] = (const float*)d_in[i++];
    bias[j] = (const float*)d_in[i++];
  }
  if (!tp && i < n_in) tp = d_in[i++];

  cudaFuncSetAttribute(fused_mlp, cudaFuncAttributeMaxDynamicSharedMemorySize, SMEM_BYTES);

  constexpr int TOTAL = N_CHUNKS * CH_H;
  prep_weights<<<(TOTAL + 255) / 256, 256>>>(W[0], W[1], W[2], W[3], W[4],
                                             W[5], W[6], W[8], W[9]);

  Params p;
  p.x = x; p.B = B; p.W0 = W[0];
  p.b0 = bias[0]; p.b1 = bias[1]; p.b2 = bias[2]; p.b3 = bias[3]; p.b4 = bias[4];
  p.bc0 = bias[5]; p.bc1 = bias[6]; p.bc2 = bias[7];
  p.bn0 = bias[8]; p.bn1 = bias[9]; p.bn2 = bias[10];
  p.Wc2 = W[7]; p.Wn2 = W[10];
  p.t = (const int*)tp;
  p.out = (float*)d_out;

  fused_mlp<<<NPTS / MT, THREADS, SMEM_BYTES>>>(p);
}